// round 1
// baseline (speedup 1.0000x reference)
#include <cuda_runtime.h>
#include <math.h>

#define HID   768
#define BATCH 4
#define SEQ   2048
#define NH    12
#define HD    64
#define MTOT  (BATCH*SEQ)          // 8192
#define NEG_BIG (-1e31f)

// Scratch for Q,K,V in [B,H,S,hd] layout (device globals: allocation-free)
__device__ float g_q[BATCH*NH*SEQ*HD];
__device__ float g_k[BATCH*NH*SEQ*HD];
__device__ float g_v[BATCH*NH*SEQ*HD];

// ---------------------------------------------------------------------------
// Kernel 1: fused QKV projection.  C[8192,2304] = toks @ [Wq|Wk|Wv] + bias,
// written permuted into g_q/g_k/g_v as [B,H,S,hd].
// Tiles: 128x128x16, 256 threads, 8x8 per thread.
// ---------------------------------------------------------------------------
__global__ void qkv_gemm_kernel(const float* __restrict__ toks,
                                const float* __restrict__ Wq, const float* __restrict__ bq,
                                const float* __restrict__ Wk, const float* __restrict__ bk,
                                const float* __restrict__ Wv, const float* __restrict__ bv) {
    __shared__ float sAT[16][128];   // A transposed: [k][m]
    __shared__ float sB[16][128];    // B: [k][n]

    const int nb  = blockIdx.x;      // 0..17  (N = 2304, 128 each)
    const int mb  = blockIdx.y;      // 0..63  (M = 8192, 128 each)
    const int tid = threadIdx.x;
    const int tx  = tid & 15;
    const int ty  = tid >> 4;

    const int w  = (nb * 128) / HID;     // 0=Q,1=K,2=V
    const int nc = (nb * 128) % HID;     // col offset inside the selected W
    const float* __restrict__ Wsel = (w == 0) ? Wq : (w == 1) ? Wk : Wv;
    const float* __restrict__ bsel = (w == 0) ? bq : (w == 1) ? bk : bv;

    float acc[8][8];
#pragma unroll
    for (int i = 0; i < 8; i++)
#pragma unroll
        for (int j = 0; j < 8; j++) acc[i][j] = 0.f;

    for (int k0 = 0; k0 < HID; k0 += 16) {
        // load A tile 128x16 (transposed into sAT)
#pragma unroll
        for (int it = 0; it < 2; it++) {
            int idx = tid + it * 256;          // 0..511
            int r = idx >> 2, q = idx & 3;     // r: row 0..127, q: k-group
            float4 a = *(const float4*)&toks[(size_t)(mb * 128 + r) * HID + k0 + q * 4];
            sAT[q * 4 + 0][r] = a.x;
            sAT[q * 4 + 1][r] = a.y;
            sAT[q * 4 + 2][r] = a.z;
            sAT[q * 4 + 3][r] = a.w;
        }
        // load B tile 16x128
#pragma unroll
        for (int it = 0; it < 2; it++) {
            int idx = tid + it * 256;
            int kr = idx >> 5, cq = idx & 31;
            float4 bvv = *(const float4*)&Wsel[(size_t)(k0 + kr) * HID + nc + cq * 4];
            sB[kr][cq * 4 + 0] = bvv.x;
            sB[kr][cq * 4 + 1] = bvv.y;
            sB[kr][cq * 4 + 2] = bvv.z;
            sB[kr][cq * 4 + 3] = bvv.w;
        }
        __syncthreads();

#pragma unroll
        for (int kk = 0; kk < 16; kk++) {
            float af[8], bf[8];
            float4 a0 = *(const float4*)&sAT[kk][ty * 8];
            float4 a1 = *(const float4*)&sAT[kk][ty * 8 + 4];
            float4 b0 = *(const float4*)&sB[kk][tx * 8];
            float4 b1 = *(const float4*)&sB[kk][tx * 8 + 4];
            af[0]=a0.x; af[1]=a0.y; af[2]=a0.z; af[3]=a0.w;
            af[4]=a1.x; af[5]=a1.y; af[6]=a1.z; af[7]=a1.w;
            bf[0]=b0.x; bf[1]=b0.y; bf[2]=b0.z; bf[3]=b0.w;
            bf[4]=b1.x; bf[5]=b1.y; bf[6]=b1.z; bf[7]=b1.w;
#pragma unroll
            for (int i = 0; i < 8; i++)
#pragma unroll
                for (int j = 0; j < 8; j++) acc[i][j] += af[i] * bf[j];
        }
        __syncthreads();
    }

    // epilogue: add bias, store permuted to [B,H,S,hd]
    const int cbase = nc + tx * 8;          // col within W (0..767), 8 consecutive
    const int h     = cbase >> 6;
    const int dbase = cbase & 63;           // 8 consecutive dims within head
    float* __restrict__ buf = (w == 0) ? g_q : (w == 1) ? g_k : g_v;

    float bias[8];
#pragma unroll
    for (int j = 0; j < 8; j++) bias[j] = bsel[cbase + j];

#pragma unroll
    for (int i = 0; i < 8; i++) {
        int m  = mb * 128 + ty * 8 + i;
        int bb = m >> 11;          // / 2048
        int ss = m & 2047;
        float* dst = &buf[((size_t)(bb * NH + h) * SEQ + ss) * HD + dbase];
        float4 v0 = make_float4(acc[i][0] + bias[0], acc[i][1] + bias[1],
                                acc[i][2] + bias[2], acc[i][3] + bias[3]);
        float4 v1 = make_float4(acc[i][4] + bias[4], acc[i][5] + bias[5],
                                acc[i][6] + bias[6], acc[i][7] + bias[7]);
        *(float4*)&dst[0] = v0;
        *(float4*)&dst[4] = v1;
    }
}

// ---------------------------------------------------------------------------
// Kernel 2: flash attention, fp32, online softmax.
// Grid: (32 q-tiles, 12 heads, 4 batches); 256 threads (16x16).
// Each thread: 4 q-rows x 4 cols microtile.
// smem: Q[64x64] + KV[64x64] (K transposed, then reused for V) + P[64x64] = 48KB.
// ---------------------------------------------------------------------------
__global__ void attn_kernel(const int* __restrict__ masks, float* __restrict__ out) {
    __shared__ float sQ [64 * 64];
    __shared__ float sKV[64 * 64];   // phase 1: K transposed [d][c]; phase 2: V [k][d]
    __shared__ float sP [64 * 64];

    const int qt  = blockIdx.x;      // 0..31
    const int h   = blockIdx.y;      // 0..11
    const int b   = blockIdx.z;      // 0..3
    const int tid = threadIdx.x;
    const int tx  = tid & 15;
    const int ty  = tid >> 4;
    const int r0  = ty * 4;          // this thread's q rows (tile-local)
    const int c0  = tx * 4;          // this thread's cols

    const size_t bh = (size_t)(b * NH + h) * SEQ;
    const float* __restrict__ Qb = g_q + (bh + qt * 64) * HD;
    const float* __restrict__ Kb = g_k + bh * HD;
    const float* __restrict__ Vb = g_v + bh * HD;
    const int*   __restrict__ mrow = masks + b * SEQ;

    // load Q tile (64x64)
#pragma unroll
    for (int it = 0; it < 4; it++) {
        int idx = tid + it * 256;         // 0..1023
        int r = idx >> 4, q = idx & 15;
        *(float4*)&sQ[r * 64 + q * 4] = *(const float4*)&Qb[r * 64 + q * 4];
    }

    float fq[4];
#pragma unroll
    for (int i = 0; i < 4; i++) fq[i] = (float)mrow[qt * 64 + r0 + i];

    float o[4][4];
    float mprev[4], lprev[4];
#pragma unroll
    for (int i = 0; i < 4; i++) {
        mprev[i] = -3.0e38f;
        lprev[i] = 0.f;
#pragma unroll
        for (int j = 0; j < 4; j++) o[i][j] = 0.f;
    }

    for (int t = 0; t < SEQ / 64; t++) {
        __syncthreads();   // prior-iter V reads done (and Q load on t==0)
        // load K tile transposed: sKV[d][c] = K[t*64+c][d]
#pragma unroll
        for (int it = 0; it < 4; it++) {
            int idx = tid + it * 256;
            int r = idx >> 4, q = idx & 15;   // r = key idx, q = dim group
            float4 kv = *(const float4*)&Kb[(size_t)(t * 64 + r) * HD + q * 4];
            sKV[(q * 4 + 0) * 64 + r] = kv.x;
            sKV[(q * 4 + 1) * 64 + r] = kv.y;
            sKV[(q * 4 + 2) * 64 + r] = kv.z;
            sKV[(q * 4 + 3) * 64 + r] = kv.w;
        }
        __syncthreads();

        float fk[4];
#pragma unroll
        for (int j = 0; j < 4; j++) fk[j] = (float)mrow[t * 64 + c0 + j];

        // S = Q K^T
        float sacc[4][4];
#pragma unroll
        for (int i = 0; i < 4; i++)
#pragma unroll
            for (int j = 0; j < 4; j++) sacc[i][j] = 0.f;

        for (int d0 = 0; d0 < 64; d0 += 4) {
            float qf[4][4], kf[4][4];
#pragma unroll
            for (int i = 0; i < 4; i++) {
                float4 qv = *(const float4*)&sQ[(r0 + i) * 64 + d0];
                qf[i][0]=qv.x; qf[i][1]=qv.y; qf[i][2]=qv.z; qf[i][3]=qv.w;
            }
#pragma unroll
            for (int dd = 0; dd < 4; dd++) {
                float4 kv = *(const float4*)&sKV[(d0 + dd) * 64 + c0];
                kf[dd][0]=kv.x; kf[dd][1]=kv.y; kf[dd][2]=kv.z; kf[dd][3]=kv.w;
            }
#pragma unroll
            for (int i = 0; i < 4; i++)
#pragma unroll
                for (int j = 0; j < 4; j++)
#pragma unroll
                    for (int dd = 0; dd < 4; dd++)
                        sacc[i][j] += qf[i][dd] * kf[dd][j];
        }

        // scale + mask + online softmax update
#pragma unroll
        for (int i = 0; i < 4; i++) {
            float mx = -3.0e38f;
#pragma unroll
            for (int j = 0; j < 4; j++) {
                float sv = sacc[i][j] * 0.125f + (1.0f - fq[i] * fk[j]) * NEG_BIG;
                sacc[i][j] = sv;
                mx = fmaxf(mx, sv);
            }
#pragma unroll
            for (int off = 1; off < 16; off <<= 1)
                mx = fmaxf(mx, __shfl_xor_sync(0xffffffffu, mx, off));
            float mnew = fmaxf(mprev[i], mx);
            float corr = __expf(mprev[i] - mnew);
            float ls = 0.f;
#pragma unroll
            for (int j = 0; j < 4; j++) {
                float p = __expf(sacc[i][j] - mnew);
                sacc[i][j] = p;
                ls += p;
            }
#pragma unroll
            for (int off = 1; off < 16; off <<= 1)
                ls += __shfl_xor_sync(0xffffffffu, ls, off);
            lprev[i] = lprev[i] * corr + ls;
            mprev[i] = mnew;
#pragma unroll
            for (int j = 0; j < 4; j++) o[i][j] *= corr;
        }

        // stage P
#pragma unroll
        for (int i = 0; i < 4; i++) {
            float4 pv = make_float4(sacc[i][0], sacc[i][1], sacc[i][2], sacc[i][3]);
            *(float4*)&sP[(r0 + i) * 64 + c0] = pv;
        }
        __syncthreads();   // P visible; K reads finished -> reuse sKV for V

        // load V tile (natural [k][d])
#pragma unroll
        for (int it = 0; it < 4; it++) {
            int idx = tid + it * 256;
            int r = idx >> 4, q = idx & 15;
            *(float4*)&sKV[r * 64 + q * 4] =
                *(const float4*)&Vb[(size_t)(t * 64 + r) * HD + q * 4];
        }
        __syncthreads();

        // O += P @ V
        for (int k0 = 0; k0 < 64; k0 += 4) {
            float pf[4][4], vf[4][4];
#pragma unroll
            for (int i = 0; i < 4; i++) {
                float4 pv = *(const float4*)&sP[(r0 + i) * 64 + k0];
                pf[i][0]=pv.x; pf[i][1]=pv.y; pf[i][2]=pv.z; pf[i][3]=pv.w;
            }
#pragma unroll
            for (int kk = 0; kk < 4; kk++) {
                float4 vv = *(const float4*)&sKV[(k0 + kk) * 64 + c0];
                vf[kk][0]=vv.x; vf[kk][1]=vv.y; vf[kk][2]=vv.z; vf[kk][3]=vv.w;
            }
#pragma unroll
            for (int i = 0; i < 4; i++)
#pragma unroll
                for (int j = 0; j < 4; j++)
#pragma unroll
                    for (int kk = 0; kk < 4; kk++)
                        o[i][j] += pf[i][kk] * vf[kk][j];
        }
    }

    // epilogue: normalize and write [B,S,H*hd]
#pragma unroll
    for (int i = 0; i < 4; i++) {
        float inv = 1.0f / lprev[i];
        int srow = qt * 64 + r0 + i;
        float4 ov = make_float4(o[i][0] * inv, o[i][1] * inv,
                                o[i][2] * inv, o[i][3] * inv);
        *(float4*)&out[((size_t)b * SEQ + srow) * HID + h * HD + c0] = ov;
    }
}

// ---------------------------------------------------------------------------
extern "C" void kernel_launch(void* const* d_in, const int* in_sizes, int n_in,
                              void* d_out, int out_size) {
    const float* toks = (const float*)d_in[0];
    const int*   masks = (const int*)d_in[1];
    const float* Wq = (const float*)d_in[2];
    const float* bq = (const float*)d_in[3];
    const float* Wk = (const float*)d_in[4];
    const float* bk = (const float*)d_in[5];
    const float* Wv = (const float*)d_in[6];
    const float* bv = (const float*)d_in[7];
    float* out = (float*)d_out;

    qkv_gemm_kernel<<<dim3(18, 64), 256>>>(toks, Wq, bq, Wk, bk, Wv, bv);
    attn_kernel<<<dim3(32, NH, BATCH), 256>>>(masks, out);
}

// round 2
// speedup vs baseline: 3.6722x; 3.6722x over previous
#include <cuda_runtime.h>
#include <math.h>
#include <stdint.h>

#define HID   768
#define BATCH 4
#define SEQ   2048
#define NH    12
#define HD    64
#define NEG_BIG (-1e31f)

// Scratch Q,K,V in [B,H,S,hd] layout (device globals: allocation-free)
__device__ float g_q[BATCH*NH*SEQ*HD];
__device__ float g_k[BATCH*NH*SEQ*HD];
__device__ float g_v[BATCH*NH*SEQ*HD];

// ---------------------------------------------------------------------------
// helpers
// ---------------------------------------------------------------------------
__device__ __forceinline__ uint32_t f2tf(float f) {
    uint32_t u;
    asm("cvt.rna.tf32.f32 %0, %1;" : "=r"(u) : "f"(f));
    return u;
}

__device__ __forceinline__ void mma_tf32(float* c, const uint32_t* a,
                                         uint32_t b0, uint32_t b1) {
    asm volatile(
        "mma.sync.aligned.m16n8k8.row.col.f32.tf32.tf32.f32 "
        "{%0,%1,%2,%3},{%4,%5,%6,%7},{%8,%9},{%0,%1,%2,%3};"
        : "+f"(c[0]), "+f"(c[1]), "+f"(c[2]), "+f"(c[3])
        : "r"(a[0]), "r"(a[1]), "r"(a[2]), "r"(a[3]), "r"(b0), "r"(b1));
}

__device__ __forceinline__ uint4 tf4(float4 v) {
    uint4 u;
    u.x = f2tf(v.x); u.y = f2tf(v.y); u.z = f2tf(v.z); u.w = f2tf(v.w);
    return u;
}

// ---------------------------------------------------------------------------
// Kernel 1: fused QKV projection with tf32 tensor cores.
// C[8192,2304] = toks @ [Wq|Wk|Wv] + bias -> permuted into g_q/g_k/g_v [B,H,S,hd]
// Block tile 128x128, K-tile 32.  256 threads = 8 warps (4 along M x 2 along N),
// warp tile 32x64 -> 2 m-blocks x 8 n-blocks of m16n8k8.
// ---------------------------------------------------------------------------
#define ASTR 36
#define BSTR 136
__global__ __launch_bounds__(256) void qkv_gemm_kernel(
        const float* __restrict__ toks,
        const float* __restrict__ Wq, const float* __restrict__ bq,
        const float* __restrict__ Wk, const float* __restrict__ bk,
        const float* __restrict__ Wv, const float* __restrict__ bv) {
    __shared__ float sA[128 * ASTR];   // [m][k] stride 36
    __shared__ float sB[32 * BSTR];    // [k][n] stride 136

    const int nbk = blockIdx.x;        // 0..17
    const int mb  = blockIdx.y;        // 0..63
    const int tid = threadIdx.x;
    const int warpId = tid >> 5;
    const int lane = tid & 31;
    const int g   = lane >> 2;
    const int tig = lane & 3;
    const int wm  = warpId >> 1;       // 0..3
    const int wn  = warpId & 1;        // 0..1

    const int w  = (nbk * 128) / HID;        // which of Q/K/V
    const int nc = (nbk * 128) % HID;
    const float* __restrict__ Wsel = (w == 0) ? Wq : (w == 1) ? Wk : Wv;
    const float* __restrict__ bsel = (w == 0) ? bq : (w == 1) ? bk : bv;

    float acc[2][8][4];
#pragma unroll
    for (int mi = 0; mi < 2; mi++)
#pragma unroll
        for (int nb = 0; nb < 8; nb++)
#pragma unroll
            for (int j = 0; j < 4; j++) acc[mi][nb][j] = 0.f;

    for (int k0 = 0; k0 < HID; k0 += 32) {
        // stage A: 128x32
#pragma unroll
        for (int i = 0; i < 4; i++) {
            int idx = tid + i * 256;           // 0..1023
            int r = idx >> 3, cg = idx & 7;
            float4 a = *(const float4*)&toks[(size_t)(mb * 128 + r) * HID + k0 + cg * 4];
            *(uint4*)&sA[r * ASTR + cg * 4] = tf4(a);
        }
        // stage B: 32x128
#pragma unroll
        for (int i = 0; i < 4; i++) {
            int idx = tid + i * 256;
            int r = idx >> 5, cg = idx & 31;
            float4 bvv = *(const float4*)&Wsel[(size_t)(k0 + r) * HID + nc + cg * 4];
            *(uint4*)&sB[r * BSTR + cg * 4] = tf4(bvv);
        }
        __syncthreads();

#pragma unroll
        for (int kc = 0; kc < 4; kc++) {
            uint32_t af[2][4];
#pragma unroll
            for (int mi = 0; mi < 2; mi++) {
                int row = wm * 32 + mi * 16;
                af[mi][0] = __float_as_uint(sA[(row + g)     * ASTR + kc * 8 + tig]);
                af[mi][1] = __float_as_uint(sA[(row + g + 8) * ASTR + kc * 8 + tig]);
                af[mi][2] = __float_as_uint(sA[(row + g)     * ASTR + kc * 8 + tig + 4]);
                af[mi][3] = __float_as_uint(sA[(row + g + 8) * ASTR + kc * 8 + tig + 4]);
            }
            uint32_t bf[8][2];
#pragma unroll
            for (int nb = 0; nb < 8; nb++) {
                int col = wn * 64 + nb * 8 + g;
                bf[nb][0] = __float_as_uint(sB[(kc * 8 + tig)     * BSTR + col]);
                bf[nb][1] = __float_as_uint(sB[(kc * 8 + tig + 4) * BSTR + col]);
            }
#pragma unroll
            for (int mi = 0; mi < 2; mi++)
#pragma unroll
                for (int nb = 0; nb < 8; nb++)
                    mma_tf32(acc[mi][nb], af[mi], bf[nb][0], bf[nb][1]);
        }
        __syncthreads();
    }

    // epilogue: bias + permuted store
    float* __restrict__ buf = (w == 0) ? g_q : (w == 1) ? g_k : g_v;
#pragma unroll
    for (int mi = 0; mi < 2; mi++) {
#pragma unroll
        for (int nb = 0; nb < 8; nb++) {
            int n = nc + wn * 64 + nb * 8 + 2 * tig;     // global col in 0..767
            int h = n >> 6;
            int d = n & 63;
            float b0v = bsel[n], b1v = bsel[n + 1];
            int row = mb * 128 + wm * 32 + mi * 16 + g;
            int bb = row >> 11;
            int ss = row & 2047;
            float* dst = &buf[((size_t)(bb * NH + h) * SEQ + ss) * HD + d];
            *(float2*)dst = make_float2(acc[mi][nb][0] + b0v, acc[mi][nb][1] + b1v);
            *(float2*)(dst + 8 * HD) = make_float2(acc[mi][nb][2] + b0v,
                                                   acc[mi][nb][3] + b1v);
        }
    }
}

// ---------------------------------------------------------------------------
// Kernel 2: flash attention with tf32 tensor cores.
// Grid (32 q-tiles, 12 heads, 4 batch), 128 threads = 4 warps; warp = 16 q rows.
// Q fragments register-resident.  K tile smem stride 68; V tile stride 72
// (both conflict-free for their B-fragment pattern).  P per-warp smem stride 68.
// ---------------------------------------------------------------------------
#define KSTR 68
#define VSTR 72
#define PSTR 68
__global__ __launch_bounds__(128) void attn_kernel(const int* __restrict__ masks,
                                                   float* __restrict__ out) {
    __shared__ float sKV[64 * VSTR];      // K phase (stride 68) then V phase (stride 72)
    __shared__ float sP[4 * 16 * PSTR];   // per-warp P tiles
    __shared__ float sMk[64];

    const int qt  = blockIdx.x;
    const int h   = blockIdx.y;
    const int b   = blockIdx.z;
    const int tid = threadIdx.x;
    const int w    = tid >> 5;
    const int lane = tid & 31;
    const int g    = lane >> 2;
    const int tig  = lane & 3;

    const size_t bh = (size_t)(b * NH + h) * SEQ;
    const float* __restrict__ Qb = g_q + (bh + qt * 64 + w * 16) * HD;
    const float* __restrict__ Kb = g_k + bh * HD;
    const float* __restrict__ Vb = g_v + bh * HD;
    const int*   __restrict__ mrow = masks + b * SEQ;

    // register-resident Q fragments (16 rows x 64 dims per warp)
    uint32_t qa[8][4];
#pragma unroll
    for (int kc = 0; kc < 8; kc++) {
        qa[kc][0] = f2tf(Qb[(size_t)g * HD + kc * 8 + tig]);
        qa[kc][1] = f2tf(Qb[(size_t)(g + 8) * HD + kc * 8 + tig]);
        qa[kc][2] = f2tf(Qb[(size_t)g * HD + kc * 8 + tig + 4]);
        qa[kc][3] = f2tf(Qb[(size_t)(g + 8) * HD + kc * 8 + tig + 4]);
    }
    const float fq0 = (float)mrow[qt * 64 + w * 16 + g];
    const float fq1 = (float)mrow[qt * 64 + w * 16 + g + 8];

    float o[8][4];
#pragma unroll
    for (int nb = 0; nb < 8; nb++)
#pragma unroll
        for (int j = 0; j < 4; j++) o[nb][j] = 0.f;
    float m0 = -3.0e38f, m1 = -3.0e38f, l0 = 0.f, l1 = 0.f;

    float* Pw = sP + w * 16 * PSTR;

    for (int t = 0; t < SEQ / 64; t++) {
        __syncthreads();                       // done reading prev V / first entry
        // stage K tile [key][dim], stride 68, tf32
#pragma unroll
        for (int i = 0; i < 8; i++) {
            int idx = tid + i * 128;
            int r = idx >> 4, cg = idx & 15;
            float4 kv = *(const float4*)&Kb[(size_t)(t * 64 + r) * HD + cg * 4];
            *(uint4*)&sKV[r * KSTR + cg * 4] = tf4(kv);
        }
        if (tid < 64) sMk[tid] = (float)mrow[t * 64 + tid];
        __syncthreads();

        // S = Q K^T  (per warp: 16x64)
        float sacc[8][4];
#pragma unroll
        for (int nb = 0; nb < 8; nb++) {
            float c[4] = {0.f, 0.f, 0.f, 0.f};
#pragma unroll
            for (int kc = 0; kc < 8; kc++) {
                uint32_t b0 = __float_as_uint(sKV[(nb * 8 + g) * KSTR + kc * 8 + tig]);
                uint32_t b1 = __float_as_uint(sKV[(nb * 8 + g) * KSTR + kc * 8 + tig + 4]);
                mma_tf32(c, qa[kc], b0, b1);
            }
            sacc[nb][0] = c[0]; sacc[nb][1] = c[1];
            sacc[nb][2] = c[2]; sacc[nb][3] = c[3];
        }

        // scale + mask + online softmax
        float mx0 = -3.0e38f, mx1 = -3.0e38f;
#pragma unroll
        for (int nb = 0; nb < 8; nb++) {
#pragma unroll
            for (int j = 0; j < 2; j++) {
                float fk = sMk[nb * 8 + 2 * tig + j];
                float s0 = sacc[nb][j]     * 0.125f + (1.0f - fq0 * fk) * NEG_BIG;
                float s1 = sacc[nb][2 + j] * 0.125f + (1.0f - fq1 * fk) * NEG_BIG;
                sacc[nb][j] = s0; sacc[nb][2 + j] = s1;
                mx0 = fmaxf(mx0, s0); mx1 = fmaxf(mx1, s1);
            }
        }
        mx0 = fmaxf(mx0, __shfl_xor_sync(0xffffffffu, mx0, 1));
        mx0 = fmaxf(mx0, __shfl_xor_sync(0xffffffffu, mx0, 2));
        mx1 = fmaxf(mx1, __shfl_xor_sync(0xffffffffu, mx1, 1));
        mx1 = fmaxf(mx1, __shfl_xor_sync(0xffffffffu, mx1, 2));

        float mn0 = fmaxf(m0, mx0), mn1 = fmaxf(m1, mx1);
        float corr0 = __expf(m0 - mn0), corr1 = __expf(m1 - mn1);
        m0 = mn0; m1 = mn1;

        float ls0 = 0.f, ls1 = 0.f;
#pragma unroll
        for (int nb = 0; nb < 8; nb++) {
#pragma unroll
            for (int j = 0; j < 2; j++) {
                float p0 = __expf(sacc[nb][j] - m0);
                float p1 = __expf(sacc[nb][2 + j] - m1);
                sacc[nb][j] = p0; sacc[nb][2 + j] = p1;
                ls0 += p0; ls1 += p1;
            }
        }
        ls0 += __shfl_xor_sync(0xffffffffu, ls0, 1);
        ls0 += __shfl_xor_sync(0xffffffffu, ls0, 2);
        ls1 += __shfl_xor_sync(0xffffffffu, ls1, 1);
        ls1 += __shfl_xor_sync(0xffffffffu, ls1, 2);
        l0 = l0 * corr0 + ls0;
        l1 = l1 * corr1 + ls1;
#pragma unroll
        for (int nb = 0; nb < 8; nb++) {
            o[nb][0] *= corr0; o[nb][1] *= corr0;
            o[nb][2] *= corr1; o[nb][3] *= corr1;
        }

        // stage P (per-warp region, tf32)
#pragma unroll
        for (int nb = 0; nb < 8; nb++) {
            *(float2*)&Pw[g * PSTR + nb * 8 + 2 * tig] =
                make_float2(__uint_as_float(f2tf(sacc[nb][0])),
                            __uint_as_float(f2tf(sacc[nb][1])));
            *(float2*)&Pw[(g + 8) * PSTR + nb * 8 + 2 * tig] =
                make_float2(__uint_as_float(f2tf(sacc[nb][2])),
                            __uint_as_float(f2tf(sacc[nb][3])));
        }
        __syncthreads();                       // all warps done reading K

        // stage V tile [key][dim], stride 72, tf32
#pragma unroll
        for (int i = 0; i < 8; i++) {
            int idx = tid + i * 128;
            int r = idx >> 4, cg = idx & 15;
            float4 vv = *(const float4*)&Vb[(size_t)(t * 64 + r) * HD + cg * 4];
            *(uint4*)&sKV[r * VSTR + cg * 4] = tf4(vv);
        }
        __syncthreads();

        // O += P @ V
#pragma unroll
        for (int kc = 0; kc < 8; kc++) {
            uint32_t pa[4];
            pa[0] = __float_as_uint(Pw[g * PSTR + kc * 8 + tig]);
            pa[1] = __float_as_uint(Pw[(g + 8) * PSTR + kc * 8 + tig]);
            pa[2] = __float_as_uint(Pw[g * PSTR + kc * 8 + tig + 4]);
            pa[3] = __float_as_uint(Pw[(g + 8) * PSTR + kc * 8 + tig + 4]);
#pragma unroll
            for (int nb = 0; nb < 8; nb++) {
                uint32_t b0 = __float_as_uint(sKV[(kc * 8 + tig)     * VSTR + nb * 8 + g]);
                uint32_t b1 = __float_as_uint(sKV[(kc * 8 + tig + 4) * VSTR + nb * 8 + g]);
                mma_tf32(o[nb], pa, b0, b1);
            }
        }
    }

    // epilogue: normalize + write [B,S,H*hd]
    float inv0 = 1.0f / l0, inv1 = 1.0f / l1;
    int row0 = qt * 64 + w * 16 + g;
#pragma unroll
    for (int nb = 0; nb < 8; nb++) {
        int d = h * HD + nb * 8 + 2 * tig;
        float* dst0 = &out[((size_t)b * SEQ + row0) * HID + d];
        float* dst1 = &out[((size_t)b * SEQ + row0 + 8) * HID + d];
        *(float2*)dst0 = make_float2(o[nb][0] * inv0, o[nb][1] * inv0);
        *(float2*)dst1 = make_float2(o[nb][2] * inv1, o[nb][3] * inv1);
    }
}

// ---------------------------------------------------------------------------
extern "C" void kernel_launch(void* const* d_in, const int* in_sizes, int n_in,
                              void* d_out, int out_size) {
    const float* toks  = (const float*)d_in[0];
    const int*   masks = (const int*)d_in[1];
    const float* Wq = (const float*)d_in[2];
    const float* bq = (const float*)d_in[3];
    const float* Wk = (const float*)d_in[4];
    const float* bk = (const float*)d_in[5];
    const float* Wv = (const float*)d_in[6];
    const float* bv = (const float*)d_in[7];
    float* out = (float*)d_out;

    qkv_gemm_kernel<<<dim3(18, 64), 256>>>(toks, Wq, bq, Wk, bk, Wv, bv);
    attn_kernel<<<dim3(32, NH, BATCH), 128>>>(masks, out);
}